// round 10
// baseline (speedup 1.0000x reference)
#include <cuda_runtime.h>
#include <cstdint>

// ============================================================================
// out = adj @ (x @ W)
//   x   [16384, 2048] f32  (d_in[0])
//   adj [16384,16384] f32  (d_in[1])
//   W   [ 2048,  512] f32  (d_in[2])
//   out [16384,  512] f32
//
// tf32 mma.sync GEMM, 64x64 warp tiles (4 warps, CTA 128x128), cp.async
// 3-stage pipeline with MMA-interleaved chunk issue (R9), frag double-
// buffering, 2 CTAs/SM.
// GEMM1 writes hT[512][16384] (transposed, tf32-pre-rounded) so GEMM2 loads
// BOTH operand tiles k-major and uses ldmatrix.x4 for A and B fragments:
// zero scalar LDS in the GEMM2 hot loop (R7 idea, now viable post-R9).
// ============================================================================

#define BM 128
#define BN 128
#define BK 32
#define NTHREADS 128
#define NCOLS 512
#define NROWS 16384
#define SA 36                  // k-major tile row stride (floats): 32 + 4 pad
#define SBKN 136               // GEMM1 B [k][n] row stride: 128 + 8 pad
#define NSTAGE 3

static constexpr int A_STAGE_F = BM * SA;                   // 4608 floats

__device__ float g_hT[(size_t)NCOLS * NROWS];               // 32 MB scratch (h^T)

__device__ __forceinline__ uint32_t f2tf(float f) {
    uint32_t u;
    asm("cvt.rna.tf32.f32 %0, %1;" : "=r"(u) : "f"(f));
    return u;
}
__device__ __forceinline__ uint32_t f2tf_u(uint32_t x) {
    return f2tf(__uint_as_float(x));
}

__device__ __forceinline__ uint32_t smem_u32(const void* p) {
    uint32_t a;
    asm("{ .reg .u64 t; cvta.to.shared.u64 t, %1; cvt.u32.u64 %0, t; }"
        : "=r"(a) : "l"(p));
    return a;
}

__device__ __forceinline__ void cp_async16(uint32_t dst, const void* src) {
    asm volatile("cp.async.cg.shared.global [%0], [%1], 16;"
                 :: "r"(dst), "l"(src));
}
__device__ __forceinline__ void cp_commit() {
    asm volatile("cp.async.commit_group;");
}
template <int N>
__device__ __forceinline__ void cp_wait() {
    asm volatile("cp.async.wait_group %0;" :: "n"(N));
}

__device__ __forceinline__ void ldsm_x4(uint32_t* r, uint32_t addr) {
    asm volatile(
        "ldmatrix.sync.aligned.m8n8.x4.shared.b16 {%0,%1,%2,%3}, [%4];"
        : "=r"(r[0]), "=r"(r[1]), "=r"(r[2]), "=r"(r[3]) : "r"(addr));
}

__device__ __forceinline__ void mma_tf32(float* d,
                                         const uint32_t* a,
                                         const uint32_t* b) {
    asm volatile(
        "mma.sync.aligned.m16n8k8.row.col.f32.tf32.tf32.f32 "
        "{%0,%1,%2,%3}, {%4,%5,%6,%7}, {%8,%9}, {%0,%1,%2,%3};"
        : "+f"(d[0]), "+f"(d[1]), "+f"(d[2]), "+f"(d[3])
        : "r"(a[0]), "r"(a[1]), "r"(a[2]), "r"(a[3]),
          "r"(b[0]), "r"(b[1]));
}

// SECOND=false: GEMM1  h^T = round_tf32((A@B)^T), B=[k][n] scalar-LDS frags,
//               cvt both operands, transposed scalar epilogue.
// SECOND=true : GEMM2  C = A@B^T with B=hT[n][k] k-major: ldmatrix for A & B,
//               cvt A only (hT pre-rounded), row-major float2 epilogue.
template <bool SECOND>
__global__ void __launch_bounds__(NTHREADS, 2)
gemm_tf32_kernel(const float* __restrict__ A, const float* __restrict__ B,
                 float* __restrict__ C, int K, int ldB, int ldC) {
    constexpr int B_STAGE_F = SECOND ? (BN * SA) : (BK * SBKN);
    constexpr int STAGE_F   = A_STAGE_F + B_STAGE_F;

    extern __shared__ float smem[];

    const int tid  = threadIdx.x;
    const int wid  = tid >> 5;           // 0..3
    const int lane = tid & 31;
    const int q    = lane >> 2;          // 0..7
    const int t    = lane & 3;           // 0..3

    const int m0 = blockIdx.y * BM;
    const int n0 = blockIdx.x * BN;
    const int wm = (wid & 1) * 64;       // 2x2 warp grid, 64x64 warp tiles
    const int wn = (wid >> 1) * 64;

    const uint32_t smem_base = smem_u32(smem);

    // ---- cp.async fill addressing ----
    const float* a_src = A + (size_t)(m0 + (tid >> 3)) * K + (tid & 7) * 4;
    const uint32_t a_dst = smem_base + ((tid >> 3) * SA + (tid & 7) * 4) * 4;

    const float* b_src;
    uint32_t b_dst;
    if (SECOND) {   // hT rows: n-major, k-contiguous — same tile shape as A
        b_src = B + (size_t)(n0 + (tid >> 3)) * ldB + (tid & 7) * 4;
        b_dst = smem_base + (A_STAGE_F + (tid >> 3) * SA + (tid & 7) * 4) * 4;
    } else {        // W rows: k-major over n
        b_src = B + (size_t)(tid >> 5) * ldB + n0 + (tid & 31) * 4;
        b_dst = smem_base + (A_STAGE_F + (tid >> 5) * SBKN + (tid & 31) * 4) * 4;
    }

    const int niter = K / BK;

    // one quarter of a stage's loads: parts 0/1 = A halves, 2/3 = B halves
    auto issue_chunk = [&](int sbuf, int kb, int part) {
        const uint32_t soff = (uint32_t)(sbuf * STAGE_F * 4);
        if (part < 2) {
            const float* as = a_src + (size_t)kb * BK;
            #pragma unroll
            for (int i = 0; i < 4; ++i) {
                int c = part * 4 + i;
                cp_async16(a_dst + soff + c * (16 * SA * 4), as + (size_t)c * 16 * K);
            }
        } else if (SECOND) {
            const float* bs = b_src + (size_t)kb * BK;
            #pragma unroll
            for (int i = 0; i < 4; ++i) {
                int c = (part - 2) * 4 + i;
                cp_async16(b_dst + soff + c * (16 * SA * 4), bs + (size_t)c * 16 * ldB);
            }
        } else {
            const float* bs = b_src + (size_t)kb * BK * ldB;
            #pragma unroll
            for (int i = 0; i < 4; ++i) {
                int c = (part - 2) * 4 + i;
                cp_async16(b_dst + soff + c * (4 * SBKN * 4), bs + (size_t)c * 4 * ldB);
            }
        }
    };
    auto issue_all = [&](int sbuf, int kb) {
        #pragma unroll
        for (int p = 0; p < 4; ++p) issue_chunk(sbuf, kb, p);
    };

    float acc[4][8][4];
    #pragma unroll
    for (int i = 0; i < 4; ++i)
        #pragma unroll
        for (int j = 0; j < 8; ++j)
            #pragma unroll
            for (int r = 0; r < 4; ++r)
                acc[i][j][r] = 0.0f;

    issue_all(0, 0); cp_commit();
    issue_all(1, 1); cp_commit();

    // A ldmatrix: row = wm + mi*16 + (lane&15), col4 = (lane>>4)*4
    const uint32_t a_lds = smem_base +
        (((wm + (lane & 15)) * SA + (lane >> 4) * 4) * 4);
    // B (SECOND) ldmatrix: tile j covers ni=2j,2j+1:
    //   row = wn + 16j + 8*(lane>>4) + (lane&7), col4 = ((lane>>3)&1)*4
    const uint32_t b_lds = smem_base +
        ((A_STAGE_F + (wn + 8 * (lane >> 4) + (lane & 7)) * SA
          + ((lane >> 3) & 1) * 4) * 4);
    // B (GEMM1) scalar frag base
    const int boff = A_STAGE_F + t * SBKN + wn + q;

    uint32_t af[2][4][4];
    uint32_t bf[2][8][2];

    int buf = 0;
    for (int it = 0; it < niter; ++it) {
        cp_wait<1>();
        __syncthreads();

        const uint32_t soff    = (uint32_t)(buf * STAGE_F * 4);
        const uint32_t a_stage = a_lds + soff;
        const uint32_t b_stage = b_lds + soff;
        const float*   Bc      = smem + buf * STAGE_F;

        auto load_frags = [&](int k, int pb) {
            if (SECOND) {
                #pragma unroll
                for (int j = 0; j < 4; ++j) {
                    uint32_t r[4];
                    ldsm_x4(r, b_stage + (uint32_t)((j * 16 * SA + k * 8) * 4));
                    bf[pb][2 * j][0]     = r[0];
                    bf[pb][2 * j][1]     = r[1];
                    bf[pb][2 * j + 1][0] = r[2];
                    bf[pb][2 * j + 1][1] = r[3];
                }
            } else {
                #pragma unroll
                for (int ni = 0; ni < 8; ++ni) {
                    const float* bb = Bc + boff + k * (8 * SBKN) + ni * 8;
                    bf[pb][ni][0] = f2tf(bb[0]);
                    bf[pb][ni][1] = f2tf(bb[4 * SBKN]);
                }
            }
            #pragma unroll
            for (int mi = 0; mi < 4; ++mi) {
                ldsm_x4(af[pb][mi], a_stage + (uint32_t)((mi * 16 * SA + k * 8) * 4));
                af[pb][mi][0] = f2tf_u(af[pb][mi][0]);
                af[pb][mi][1] = f2tf_u(af[pb][mi][1]);
                af[pb][mi][2] = f2tf_u(af[pb][mi][2]);
                af[pb][mi][3] = f2tf_u(af[pb][mi][3]);
            }
        };

        // critical path first: k8=0 fragments hit an empty MIO queue
        load_frags(0, 0);

        const bool do_issue = (it + 2 < niter);
        int nb = buf + 2; if (nb >= NSTAGE) nb -= NSTAGE;

        #pragma unroll
        for (int k8 = 0; k8 < 4; ++k8) {
            const int cur = k8 & 1;
            if (k8 < 3) load_frags(k8 + 1, cur ^ 1);
            #pragma unroll
            for (int mi = 0; mi < 4; ++mi)
                #pragma unroll
                for (int ni = 0; ni < 8; ++ni)
                    mma_tf32(acc[mi][ni], af[cur][mi], bf[cur][ni]);
            // interleave a quarter of next-next stage's loads behind the MMAs
            if (do_issue) issue_chunk(nb, it + 2, k8);
        }
        cp_commit();

        if (++buf >= NSTAGE) buf = 0;
    }

    // ---- epilogue ----
    #pragma unroll
    for (int mi = 0; mi < 4; ++mi) {
        #pragma unroll
        for (int ni = 0; ni < 8; ++ni) {
            const int m = m0 + wm + mi * 16 + q;
            const int n = n0 + wn + ni * 8 + 2 * t;
            if (SECOND) {
                *(float2*)(C + (size_t)m * ldC + n) =
                    make_float2(acc[mi][ni][0], acc[mi][ni][1]);
                *(float2*)(C + (size_t)(m + 8) * ldC + n) =
                    make_float2(acc[mi][ni][2], acc[mi][ni][3]);
            } else {
                // write h^T, tf32-pre-rounded: C[n*ldC + m]
                C[(size_t)n * ldC + m] =
                    __uint_as_float(f2tf(acc[mi][ni][0]));
                C[(size_t)(n + 1) * ldC + m] =
                    __uint_as_float(f2tf(acc[mi][ni][1]));
                C[(size_t)n * ldC + m + 8] =
                    __uint_as_float(f2tf(acc[mi][ni][2]));
                C[(size_t)(n + 1) * ldC + m + 8] =
                    __uint_as_float(f2tf(acc[mi][ni][3]));
            }
        }
    }
}

// ---------------------------------------------------------------------------
extern "C" void kernel_launch(void* const* d_in, const int* in_sizes, int n_in,
                              void* d_out, int out_size) {
    const float* x   = (const float*)d_in[0];   // [16384, 2048]
    const float* adj = (const float*)d_in[1];   // [16384, 16384]
    const float* W   = (const float*)d_in[2];   // [2048, 512]
    float* out = (float*)d_out;                 // [16384, 512]

    float* hT;
    cudaGetSymbolAddress((void**)&hT, g_hT);

    constexpr int SMEM1 = NSTAGE * (A_STAGE_F + BK * SBKN) * 4;  // 107520
    constexpr int SMEM2 = NSTAGE * (A_STAGE_F + BN * SA) * 4;    // 110592

    cudaFuncSetAttribute(gemm_tf32_kernel<false>,
                         cudaFuncAttributeMaxDynamicSharedMemorySize, SMEM1);
    cudaFuncSetAttribute(gemm_tf32_kernel<true>,
                         cudaFuncAttributeMaxDynamicSharedMemorySize, SMEM2);

    dim3 grid(NCOLS / BN, NROWS / BM);   // (4, 128)

    // hT = round_tf32((x @ W)^T)
    gemm_tf32_kernel<false><<<grid, NTHREADS, SMEM1>>>(
        x, W, hT, 2048, NCOLS, NROWS);
    // out = adj @ hT^T  (A and B fragments both via ldmatrix)
    gemm_tf32_kernel<true><<<grid, NTHREADS, SMEM2>>>(
        adj, hT, out, NROWS, NROWS, NCOLS);
}

// round 14
// speedup vs baseline: 1.1405x; 1.1405x over previous
#include <cuda_runtime.h>
#include <cstdint>

// ============================================================================
// out = adj @ (x @ W)
//   x   [16384, 2048] f32  (d_in[0])
//   adj [16384,16384] f32  (d_in[1])
//   W   [ 2048,  512] f32  (d_in[2])
//   out [16384,  512] f32
//
// tf32 mma.sync GEMM (R9 base: 64x64 warp tiles, 4 warps, CTA 128x128,
// cp.async 3-stage pipeline with MMA-interleaved chunk issue, frag double-
// buffering, 2 CTAs/SM, scalar-LDS B fragments).
// Round 11: split-K=4 on GEMM2. grid 512 -> 2048 CTAs kills the 2-wave
// quantization loss (86.5% -> 98.8% chip utilization). Partials summed by a
// small reduction kernel (deterministic, no atomics).
// ============================================================================

#define BM 128
#define BN 128
#define BK 32
#define NTHREADS 128
#define NCOLS 512
#define NROWS 16384
#define SA 36                  // A smem row stride (floats): 32 + 4 pad
#define SB 136                 // B smem row stride (floats): 128 + 8 pad (conflict-free)
#define NSTAGE 3
#define NSPLIT 4               // GEMM2 K-splits

static constexpr int A_STAGE_F   = BM * SA;                 // 4608 floats
static constexpr int B_STAGE_F   = BK * SB;                 // 4352 floats
static constexpr int STAGE_F     = A_STAGE_F + B_STAGE_F;   // 8960 floats
static constexpr int SMEM_BYTES  = NSTAGE * STAGE_F * 4;    // 107520 B
static constexpr size_t OUT_ELEMS = (size_t)NROWS * NCOLS;  // 8388608

__device__ float g_h[OUT_ELEMS];                            // 32 MB scratch (h)
__device__ float g_part[NSPLIT * OUT_ELEMS];                // 128 MB partials

__device__ __forceinline__ uint32_t f2tf(float f) {
    uint32_t u;
    asm("cvt.rna.tf32.f32 %0, %1;" : "=r"(u) : "f"(f));
    return u;
}
__device__ __forceinline__ uint32_t f2tf_u(uint32_t x) {
    return f2tf(__uint_as_float(x));
}

__device__ __forceinline__ uint32_t smem_u32(const void* p) {
    uint32_t a;
    asm("{ .reg .u64 t; cvta.to.shared.u64 t, %1; cvt.u32.u64 %0, t; }"
        : "=r"(a) : "l"(p));
    return a;
}

__device__ __forceinline__ void cp_async16(uint32_t dst, const void* src) {
    asm volatile("cp.async.cg.shared.global [%0], [%1], 16;"
                 :: "r"(dst), "l"(src));
}
__device__ __forceinline__ void cp_commit() {
    asm volatile("cp.async.commit_group;");
}
template <int N>
__device__ __forceinline__ void cp_wait() {
    asm volatile("cp.async.wait_group %0;" :: "n"(N));
}

__device__ __forceinline__ void ldsm_x4(uint32_t* r, uint32_t addr) {
    asm volatile(
        "ldmatrix.sync.aligned.m8n8.x4.shared.b16 {%0,%1,%2,%3}, [%4];"
        : "=r"(r[0]), "=r"(r[1]), "=r"(r[2]), "=r"(r[3]) : "r"(addr));
}

__device__ __forceinline__ void mma_tf32(float* d,
                                         const uint32_t* a,
                                         const uint32_t* b) {
    asm volatile(
        "mma.sync.aligned.m16n8k8.row.col.f32.tf32.tf32.f32 "
        "{%0,%1,%2,%3}, {%4,%5,%6,%7}, {%8,%9}, {%0,%1,%2,%3};"
        : "+f"(d[0]), "+f"(d[1]), "+f"(d[2]), "+f"(d[3])
        : "r"(a[0]), "r"(a[1]), "r"(a[2]), "r"(a[3]),
          "r"(b[0]), "r"(b[1]));
}

// C_base points at the per-split output block:
//   split = blockIdx.z; this CTA covers K rows [z*kslice, (z+1)*kslice) of the
//   reduction and writes C_base + z*OUT_ELEMS.
// CVT_B: convert B operand from fp32 at fragment load (h is pre-rounded).
// ROUND_OUT: write C tf32-pre-rounded (GEMM1 only).
template <bool CVT_B, bool ROUND_OUT>
__global__ void __launch_bounds__(NTHREADS, 2)
gemm_tf32_kernel(const float* __restrict__ A, const float* __restrict__ B,
                 float* __restrict__ C, int kslice, int ldA,
                 size_t c_split_stride) {
    extern __shared__ float smem[];

    const int tid  = threadIdx.x;
    const int wid  = tid >> 5;           // 0..3
    const int lane = tid & 31;
    const int q    = lane >> 2;          // 0..7
    const int t    = lane & 3;           // 0..3

    const int m0 = blockIdx.y * BM;
    const int n0 = blockIdx.x * BN;
    const int wm = (wid & 1) * 64;       // 2x2 warp grid, 64x64 warp tiles
    const int wn = (wid >> 1) * 64;
    const int kstart = blockIdx.z * kslice;

    float* Cw = C + (size_t)blockIdx.z * c_split_stride;

    const float* a_src = A + (size_t)(m0 + (tid >> 3)) * ldA + kstart + (tid & 7) * 4;
    const float* b_src = B + (size_t)(kstart + (tid >> 5)) * NCOLS + n0 + (tid & 31) * 4;
    const uint32_t smem_base = smem_u32(smem);
    const uint32_t a_dst = smem_base + ((tid >> 3) * SA + (tid & 7) * 4) * 4;
    const uint32_t b_dst = smem_base + (A_STAGE_F + (tid >> 5) * SB + (tid & 31) * 4) * 4;

    const int niter = kslice / BK;

    // one quarter of a stage's loads: parts 0/1 = A halves, 2/3 = B halves
    auto issue_chunk = [&](int sbuf, int kb, int part) {
        const uint32_t soff = (uint32_t)(sbuf * STAGE_F * 4);
        if (part < 2) {
            const float* as = a_src + (size_t)kb * BK;
            #pragma unroll
            for (int i = 0; i < 4; ++i) {
                int c = part * 4 + i;
                cp_async16(a_dst + soff + c * (16 * SA * 4), as + (size_t)c * 16 * ldA);
            }
        } else {
            const float* bs = b_src + (size_t)kb * BK * NCOLS;
            #pragma unroll
            for (int i = 0; i < 4; ++i) {
                int c = (part - 2) * 4 + i;
                cp_async16(b_dst + soff + c * (4 * SB * 4), bs + (size_t)c * 4 * NCOLS);
            }
        }
    };
    auto issue_all = [&](int sbuf, int kb) {
        #pragma unroll
        for (int p = 0; p < 4; ++p) issue_chunk(sbuf, kb, p);
    };

    float acc[4][8][4];
    #pragma unroll
    for (int i = 0; i < 4; ++i)
        #pragma unroll
        for (int j = 0; j < 8; ++j)
            #pragma unroll
            for (int r = 0; r < 4; ++r)
                acc[i][j][r] = 0.0f;

    issue_all(0, 0); cp_commit();
    issue_all(1, 1); cp_commit();

    // ldmatrix lane addressing: row = wm + mi*16 + (lane&15), col4 = (lane>>4)*4
    const uint32_t a_lds = smem_base +
        (((wm + (lane & 15)) * SA + (lane >> 4) * 4) * 4);
    const int boff = A_STAGE_F + t * SB + wn + q;

    uint32_t af[2][4][4];
    uint32_t bf[2][8][2];

    int buf = 0;
    for (int it = 0; it < niter; ++it) {
        cp_wait<1>();
        __syncthreads();

        const uint32_t a_stage = a_lds + (uint32_t)(buf * STAGE_F * 4);
        const float*   Bc      = smem + buf * STAGE_F;

        auto load_frags = [&](int k, int pb) {
            #pragma unroll
            for (int mi = 0; mi < 4; ++mi) {
                ldsm_x4(af[pb][mi], a_stage + (uint32_t)((mi * 16 * SA + k * 8) * 4));
                af[pb][mi][0] = f2tf_u(af[pb][mi][0]);
                af[pb][mi][1] = f2tf_u(af[pb][mi][1]);
                af[pb][mi][2] = f2tf_u(af[pb][mi][2]);
                af[pb][mi][3] = f2tf_u(af[pb][mi][3]);
            }
            #pragma unroll
            for (int ni = 0; ni < 8; ++ni) {
                const float* bb = Bc + boff + k * (8 * SB) + ni * 8;
                if (CVT_B) {
                    bf[pb][ni][0] = f2tf(bb[0]);
                    bf[pb][ni][1] = f2tf(bb[4 * SB]);
                } else {
                    bf[pb][ni][0] = ((const uint32_t*)bb)[0];
                    bf[pb][ni][1] = ((const uint32_t*)bb)[4 * SB];
                }
            }
        };

        // critical path first: k8=0 fragments hit an empty MIO queue
        load_frags(0, 0);

        const bool do_issue = (it + 2 < niter);
        int nb = buf + 2; if (nb >= NSTAGE) nb -= NSTAGE;

        #pragma unroll
        for (int k8 = 0; k8 < 4; ++k8) {
            const int cur = k8 & 1;
            if (k8 < 3) load_frags(k8 + 1, cur ^ 1);
            #pragma unroll
            for (int mi = 0; mi < 4; ++mi)
                #pragma unroll
                for (int ni = 0; ni < 8; ++ni)
                    mma_tf32(acc[mi][ni], af[cur][mi], bf[cur][ni]);
            // interleave a quarter of next-next stage's loads behind the MMAs
            if (do_issue) issue_chunk(nb, it + 2, k8);
        }
        cp_commit();

        if (++buf >= NSTAGE) buf = 0;
    }

    // ---- epilogue: row-major, float2 stores ----
    #pragma unroll
    for (int mi = 0; mi < 4; ++mi) {
        #pragma unroll
        for (int ni = 0; ni < 8; ++ni) {
            const int m = m0 + wm + mi * 16 + q;
            const int n = n0 + wn + ni * 8 + 2 * t;
            float v0 = acc[mi][ni][0], v1 = acc[mi][ni][1];
            float v2 = acc[mi][ni][2], v3 = acc[mi][ni][3];
            if (ROUND_OUT) {
                v0 = __uint_as_float(f2tf(v0));
                v1 = __uint_as_float(f2tf(v1));
                v2 = __uint_as_float(f2tf(v2));
                v3 = __uint_as_float(f2tf(v3));
            }
            *(float2*)(Cw + (size_t)m * NCOLS + n)       = make_float2(v0, v1);
            *(float2*)(Cw + (size_t)(m + 8) * NCOLS + n) = make_float2(v2, v3);
        }
    }
}

// out = sum of NSPLIT partials, vectorized float4
__global__ void __launch_bounds__(256)
reduce_kernel(const float* __restrict__ part, float* __restrict__ out) {
    size_t i = ((size_t)blockIdx.x * 256 + threadIdx.x) * 4;
    float4 s = *(const float4*)(part + i);
    #pragma unroll
    for (int p = 1; p < NSPLIT; ++p) {
        float4 v = *(const float4*)(part + p * OUT_ELEMS + i);
        s.x += v.x; s.y += v.y; s.z += v.z; s.w += v.w;
    }
    *(float4*)(out + i) = s;
}

// ---------------------------------------------------------------------------
extern "C" void kernel_launch(void* const* d_in, const int* in_sizes, int n_in,
                              void* d_out, int out_size) {
    const float* x   = (const float*)d_in[0];   // [16384, 2048]
    const float* adj = (const float*)d_in[1];   // [16384, 16384]
    const float* W   = (const float*)d_in[2];   // [2048, 512]
    float* out = (float*)d_out;                 // [16384, 512]

    float *h, *part;
    cudaGetSymbolAddress((void**)&h, g_h);
    cudaGetSymbolAddress((void**)&part, g_part);

    cudaFuncSetAttribute(gemm_tf32_kernel<true, true>,
                         cudaFuncAttributeMaxDynamicSharedMemorySize, SMEM_BYTES);
    cudaFuncSetAttribute(gemm_tf32_kernel<false, false>,
                         cudaFuncAttributeMaxDynamicSharedMemorySize, SMEM_BYTES);

    // GEMM1: h = round_tf32(x @ W), single K-slice (grid 512)
    dim3 grid1(NCOLS / BN, NROWS / BM, 1);
    gemm_tf32_kernel<true, true><<<grid1, NTHREADS, SMEM_BYTES>>>(
        x, W, h, 2048, 2048, 0);

    // GEMM2: partials[z] = adj[:, z*4096:(z+1)*4096] @ h[z*4096:(z+1)*4096, :]
    dim3 grid2(NCOLS / BN, NROWS / BM, NSPLIT);   // 2048 CTAs -> 98.8% util
    gemm_tf32_kernel<false, false><<<grid2, NTHREADS, SMEM_BYTES>>>(
        adj, h, part, NROWS / NSPLIT, NROWS, OUT_ELEMS);

    // out = sum(partials)
    reduce_kernel<<<(int)(OUT_ELEMS / (256 * 4)), 256>>>(part, out);
}

// round 15
// speedup vs baseline: 1.2156x; 1.0658x over previous
#include <cuda_runtime.h>
#include <cstdint>

// ============================================================================
// out = adj @ (x @ W)
//   x   [16384, 2048] f32  (d_in[0])
//   adj [16384,16384] f32  (d_in[1])
//   W   [ 2048,  512] f32  (d_in[2])
//   out [16384,  512] f32
//
// R14 base (tf32 mma.sync, 64x64 warp tiles, CTA 128x128, 3-stage cp.async
// with MMA-interleaved issue, frag double-buffer, 2 CTAs/SM, split-K=4 GEMM2).
// Round 15: GEMM1 and GEMM2 fused into ONE kernel launch with device-side
// dependency counters: 512 producer CTAs (h tiles, z-major order) + 2048
// consumer CTAs (split-K GEMM2, z-ascending). Consumers spin on cnt[z]==128.
// Producers all have lower blockIdx -> dispatched first -> no deadlock.
// GEMM1's serial 198us phase now overlaps consumer work.
// ============================================================================

#define BM 128
#define BN 128
#define BK 32
#define NTHREADS 128
#define NCOLS 512
#define NROWS 16384
#define SA 36                  // A smem row stride (floats): 32 + 4 pad
#define SB 136                 // B smem row stride (floats): 128 + 8 pad
#define NSTAGE 3
#define NSPLIT 4               // GEMM2 K-splits
#define PROD_CTAS 512          // GEMM1: 128 m-tiles x 4 n-tiles
#define PROD_PER_SPLIT 128     // producers covering one split's h rows

static constexpr int A_STAGE_F   = BM * SA;                 // 4608 floats
static constexpr int B_STAGE_F   = BK * SB;                 // 4352 floats
static constexpr int STAGE_F     = A_STAGE_F + B_STAGE_F;   // 8960 floats
static constexpr int SMEM_BYTES  = NSTAGE * STAGE_F * 4;    // 107520 B
static constexpr size_t OUT_ELEMS = (size_t)NROWS * NCOLS;  // 8388608

__device__ float g_h[OUT_ELEMS];                            // 32 MB scratch (h)
__device__ float g_part[NSPLIT * OUT_ELEMS];                // 128 MB partials
__device__ int   g_cnt[NSPLIT];                             // producer counters

__device__ __forceinline__ uint32_t f2tf(float f) {
    uint32_t u;
    asm("cvt.rna.tf32.f32 %0, %1;" : "=r"(u) : "f"(f));
    return u;
}
__device__ __forceinline__ uint32_t f2tf_u(uint32_t x) {
    return f2tf(__uint_as_float(x));
}

__device__ __forceinline__ uint32_t smem_u32(const void* p) {
    uint32_t a;
    asm("{ .reg .u64 t; cvta.to.shared.u64 t, %1; cvt.u32.u64 %0, t; }"
        : "=r"(a) : "l"(p));
    return a;
}

__device__ __forceinline__ void cp_async16(uint32_t dst, const void* src) {
    asm volatile("cp.async.cg.shared.global [%0], [%1], 16;"
                 :: "r"(dst), "l"(src));
}
__device__ __forceinline__ void cp_commit() {
    asm volatile("cp.async.commit_group;");
}
template <int N>
__device__ __forceinline__ void cp_wait() {
    asm volatile("cp.async.wait_group %0;" :: "n"(N));
}

__device__ __forceinline__ void ldsm_x4(uint32_t* r, uint32_t addr) {
    asm volatile(
        "ldmatrix.sync.aligned.m8n8.x4.shared.b16 {%0,%1,%2,%3}, [%4];"
        : "=r"(r[0]), "=r"(r[1]), "=r"(r[2]), "=r"(r[3]) : "r"(addr));
}

__device__ __forceinline__ void mma_tf32(float* d,
                                         const uint32_t* a,
                                         const uint32_t* b) {
    asm volatile(
        "mma.sync.aligned.m16n8k8.row.col.f32.tf32.tf32.f32 "
        "{%0,%1,%2,%3}, {%4,%5,%6,%7}, {%8,%9}, {%0,%1,%2,%3};"
        : "+f"(d[0]), "+f"(d[1]), "+f"(d[2]), "+f"(d[3])
        : "r"(a[0]), "r"(a[1]), "r"(a[2]), "r"(a[3]),
          "r"(b[0]), "r"(b[1]));
}

// One 128x128 output tile of C = A[BM, K] @ B[K, 512-slab], A row-major with
// leading dim ldA, B row-major [k][n] with row length NCOLS. A and B already
// offset to this tile's k-origin. CVT_B: tf32-convert B fragments at load.
// ROUND_OUT: write C tf32-pre-rounded.
template <bool CVT_B, bool ROUND_OUT>
__device__ __forceinline__ void gemm_body(
    const float* __restrict__ A, const float* __restrict__ B,
    float* __restrict__ C, int niter, int ldA, int m0, int n0, float* smem) {

    const int tid  = threadIdx.x;
    const int wid  = tid >> 5;           // 0..3
    const int lane = tid & 31;
    const int q    = lane >> 2;          // 0..7
    const int t    = lane & 3;           // 0..3
    const int wm   = (wid & 1) * 64;     // 2x2 warp grid, 64x64 warp tiles
    const int wn   = (wid >> 1) * 64;

    const float* a_src = A + (size_t)(m0 + (tid >> 3)) * ldA + (tid & 7) * 4;
    const float* b_src = B + (size_t)(tid >> 5) * NCOLS + n0 + (tid & 31) * 4;
    const uint32_t smem_base = smem_u32(smem);
    const uint32_t a_dst = smem_base + ((tid >> 3) * SA + (tid & 7) * 4) * 4;
    const uint32_t b_dst = smem_base + (A_STAGE_F + (tid >> 5) * SB + (tid & 31) * 4) * 4;

    // one quarter of a stage's loads: parts 0/1 = A halves, 2/3 = B halves
    auto issue_chunk = [&](int sbuf, int kb, int part) {
        const uint32_t soff = (uint32_t)(sbuf * STAGE_F * 4);
        if (part < 2) {
            const float* as = a_src + (size_t)kb * BK;
            #pragma unroll
            for (int i = 0; i < 4; ++i) {
                int c = part * 4 + i;
                cp_async16(a_dst + soff + c * (16 * SA * 4), as + (size_t)c * 16 * ldA);
            }
        } else {
            const float* bs = b_src + (size_t)kb * BK * NCOLS;
            #pragma unroll
            for (int i = 0; i < 4; ++i) {
                int c = (part - 2) * 4 + i;
                cp_async16(b_dst + soff + c * (4 * SB * 4), bs + (size_t)c * 4 * NCOLS);
            }
        }
    };
    auto issue_all = [&](int sbuf, int kb) {
        #pragma unroll
        for (int p = 0; p < 4; ++p) issue_chunk(sbuf, kb, p);
    };

    float acc[4][8][4];
    #pragma unroll
    for (int i = 0; i < 4; ++i)
        #pragma unroll
        for (int j = 0; j < 8; ++j)
            #pragma unroll
            for (int r = 0; r < 4; ++r)
                acc[i][j][r] = 0.0f;

    issue_all(0, 0); cp_commit();
    issue_all(1, 1); cp_commit();

    // ldmatrix lane addressing: row = wm + mi*16 + (lane&15), col4 = (lane>>4)*4
    const uint32_t a_lds = smem_base +
        (((wm + (lane & 15)) * SA + (lane >> 4) * 4) * 4);
    const int boff = A_STAGE_F + t * SB + wn + q;

    uint32_t af[2][4][4];
    uint32_t bf[2][8][2];

    int buf = 0;
    for (int it = 0; it < niter; ++it) {
        cp_wait<1>();
        __syncthreads();

        const uint32_t a_stage = a_lds + (uint32_t)(buf * STAGE_F * 4);
        const float*   Bc      = smem + buf * STAGE_F;

        auto load_frags = [&](int k, int pb) {
            #pragma unroll
            for (int mi = 0; mi < 4; ++mi) {
                ldsm_x4(af[pb][mi], a_stage + (uint32_t)((mi * 16 * SA + k * 8) * 4));
                af[pb][mi][0] = f2tf_u(af[pb][mi][0]);
                af[pb][mi][1] = f2tf_u(af[pb][mi][1]);
                af[pb][mi][2] = f2tf_u(af[pb][mi][2]);
                af[pb][mi][3] = f2tf_u(af[pb][mi][3]);
            }
            #pragma unroll
            for (int ni = 0; ni < 8; ++ni) {
                const float* bb = Bc + boff + k * (8 * SB) + ni * 8;
                if (CVT_B) {
                    bf[pb][ni][0] = f2tf(bb[0]);
                    bf[pb][ni][1] = f2tf(bb[4 * SB]);
                } else {
                    bf[pb][ni][0] = ((const uint32_t*)bb)[0];
                    bf[pb][ni][1] = ((const uint32_t*)bb)[4 * SB];
                }
            }
        };

        // critical path first: k8=0 fragments hit an empty MIO queue
        load_frags(0, 0);

        const bool do_issue = (it + 2 < niter);
        int nb = buf + 2; if (nb >= NSTAGE) nb -= NSTAGE;

        #pragma unroll
        for (int k8 = 0; k8 < 4; ++k8) {
            const int cur = k8 & 1;
            if (k8 < 3) load_frags(k8 + 1, cur ^ 1);
            #pragma unroll
            for (int mi = 0; mi < 4; ++mi)
                #pragma unroll
                for (int ni = 0; ni < 8; ++ni)
                    mma_tf32(acc[mi][ni], af[cur][mi], bf[cur][ni]);
            // interleave a quarter of next-next stage's loads behind the MMAs
            if (do_issue) issue_chunk(nb, it + 2, k8);
        }
        cp_commit();

        if (++buf >= NSTAGE) buf = 0;
    }

    // ---- epilogue: row-major, float2 stores ----
    #pragma unroll
    for (int mi = 0; mi < 4; ++mi) {
        #pragma unroll
        for (int ni = 0; ni < 8; ++ni) {
            const int m = m0 + wm + mi * 16 + q;
            const int n = n0 + wn + ni * 8 + 2 * t;
            float v0 = acc[mi][ni][0], v1 = acc[mi][ni][1];
            float v2 = acc[mi][ni][2], v3 = acc[mi][ni][3];
            if (ROUND_OUT) {
                v0 = __uint_as_float(f2tf(v0));
                v1 = __uint_as_float(f2tf(v1));
                v2 = __uint_as_float(f2tf(v2));
                v3 = __uint_as_float(f2tf(v3));
            }
            *(float2*)(C + (size_t)m * NCOLS + n)       = make_float2(v0, v1);
            *(float2*)(C + (size_t)(m + 8) * NCOLS + n) = make_float2(v2, v3);
        }
    }
}

// ---------------------------------------------------------------------------
// Fused kernel: blockIdx.x < 512 -> GEMM1 producer tile (h), else GEMM2
// consumer tile gated on its split's producer counter.
// ---------------------------------------------------------------------------
__global__ void __launch_bounds__(NTHREADS, 2)
fused_kernel(const float* __restrict__ x, const float* __restrict__ adj,
             const float* __restrict__ W) {
    extern __shared__ float smem[];
    const int b = blockIdx.x;

    if (b < PROD_CTAS) {
        // ---- producer: h tile. z-major order so split z's producers are
        //      the contiguous block b in [z*128, (z+1)*128). ----
        const int z  = b >> 7;
        const int mt = (z << 5) | ((b >> 2) & 31);
        const int nt = b & 3;
        gemm_body<true, true>(x, W, g_h, 2048 / BK, 2048,
                              mt * BM, nt * BN, smem);
        __threadfence();          // all threads: publish own h stores
        __syncthreads();
        if (threadIdx.x == 0) atomicAdd(&g_cnt[z], 1);
    } else {
        // ---- consumer: GEMM2 split-K tile, z ascending ----
        const int qq = b - PROD_CTAS;
        const int z  = qq >> 9;
        const int r  = qq & 511;
        const int mt = r >> 2;
        const int nt = r & 3;

        if (threadIdx.x == 0) {
            volatile int* c = g_cnt;
            while (c[z] < PROD_PER_SPLIT)
                asm volatile("nanosleep.u32 1024;");
        }
        __syncthreads();
        __threadfence();          // acquire: order h reads after flag

        const float* A = adj + (size_t)z * (NROWS / NSPLIT);
        const float* B = g_h + (size_t)z * (NROWS / NSPLIT) * NCOLS;
        float*       C = g_part + (size_t)z * OUT_ELEMS;
        gemm_body<false, false>(A, B, C, (NROWS / NSPLIT) / BK, NROWS,
                                mt * BM, nt * BN, smem);
    }
}

__global__ void zero_cnt_kernel() {
    if (threadIdx.x < NSPLIT) g_cnt[threadIdx.x] = 0;
}

// out = sum of NSPLIT partials, vectorized float4
__global__ void __launch_bounds__(256)
reduce_kernel(const float* __restrict__ part, float* __restrict__ out) {
    size_t i = ((size_t)blockIdx.x * 256 + threadIdx.x) * 4;
    float4 s = *(const float4*)(part + i);
    #pragma unroll
    for (int p = 1; p < NSPLIT; ++p) {
        float4 v = *(const float4*)(part + p * OUT_ELEMS + i);
        s.x += v.x; s.y += v.y; s.z += v.z; s.w += v.w;
    }
    *(float4*)(out + i) = s;
}

// ---------------------------------------------------------------------------
extern "C" void kernel_launch(void* const* d_in, const int* in_sizes, int n_in,
                              void* d_out, int out_size) {
    const float* x   = (const float*)d_in[0];   // [16384, 2048]
    const float* adj = (const float*)d_in[1];   // [16384, 16384]
    const float* W   = (const float*)d_in[2];   // [2048, 512]
    float* out = (float*)d_out;                 // [16384, 512]

    float* part;
    cudaGetSymbolAddress((void**)&part, g_part);

    cudaFuncSetAttribute(fused_kernel,
                         cudaFuncAttributeMaxDynamicSharedMemorySize, SMEM_BYTES);

    // reset producer counters (graph replays reuse device globals)
    zero_cnt_kernel<<<1, 32>>>();

    // producers (512) + consumers (2048) in one launch
    fused_kernel<<<PROD_CTAS + NSPLIT * 512, NTHREADS, SMEM_BYTES>>>(x, adj, W);

    // out = sum(partials)
    reduce_kernel<<<(int)(OUT_ELEMS / (256 * 4)), 256>>>(part, out);
}